// round 4
// baseline (speedup 1.0000x reference)
#include <cuda_runtime.h>
#include <math.h>

// Problem constants (fixed by the dataset)
#define NN   100000
#define EE   1600000
#define ETOT (EE + NN)          // edges + self loops
#define F1   128                // input features
#define F2   256                // HEADS*HID
#define NEG_SLOPE 0.2f

// ---------------- scratch (device globals; no allocations allowed) ----------
__device__ float g_h1[(size_t)NN * F2];   // layer1 linear output  [N,256]
__device__ float g_h2[(size_t)NN * F2];   // elu(agg1 + b1)        [N,256]
__device__ float g_as1[NN * 4];
__device__ float g_ad1[NN * 4];
__device__ float g_h3[NN * 2];
__device__ float g_as2[NN];
__device__ float g_ad2[NN];
__device__ int   g_cnt[NN];
__device__ int   g_rowptr[NN + 1];
__device__ int   g_cursor[NN];
__device__ int   g_csr[ETOT];             // src node id per incoming edge, grouped by dst

__device__ __forceinline__ float lrelu(float x) { return x > 0.f ? x : NEG_SLOPE * x; }
__device__ __forceinline__ float elu1(float x)  { return x > 0.f ? x : expm1f(x); }

// ---------------- CSR construction ------------------------------------------
__global__ void k_init_cnt() {
    int i = blockIdx.x * blockDim.x + threadIdx.x;
    if (i < NN) g_cnt[i] = 1;   // self loop
}

__global__ void k_degree(const int* __restrict__ ei) {
    int i = blockIdx.x * blockDim.x + threadIdx.x;
    if (i < EE) atomicAdd(&g_cnt[ei[EE + i]], 1);
}

// single-block exclusive scan over g_cnt -> g_rowptr / g_cursor
__global__ void k_scan() {
    __shared__ int part[1024];
    int tid = threadIdx.x;
    const int chunk = (NN + 1023) / 1024;
    int start = tid * chunk;
    int end   = min(start + chunk, NN);
    int sum = 0;
    for (int i = start; i < end; i++) sum += g_cnt[i];
    part[tid] = sum;
    __syncthreads();
    for (int off = 1; off < 1024; off <<= 1) {
        int v = 0;
        if (tid >= off) v = part[tid - off];
        __syncthreads();
        if (tid >= off) part[tid] += v;
        __syncthreads();
    }
    int run = (tid == 0) ? 0 : part[tid - 1];
    for (int i = start; i < end; i++) {
        g_rowptr[i] = run;
        g_cursor[i] = run;
        run += g_cnt[i];
    }
    if (tid == 1023) g_rowptr[NN] = part[1023];
}

__global__ void k_scatter(const int* __restrict__ ei) {
    int i = blockIdx.x * blockDim.x + threadIdx.x;
    if (i < EE) {
        int s = ei[i];
        int d = ei[EE + i];
        int p = atomicAdd(&g_cursor[d], 1);
        g_csr[p] = s;
    } else if (i < ETOT) {
        int n = i - EE;
        int p = atomicAdd(&g_cursor[n], 1);
        g_csr[p] = n;   // self loop
    }
}

// ---------------- GEMM1: h1 = x @ W1  (100000x128 @ 128x256) ---------------
#define BM 64
#define BN 64
#define BK 16
__global__ __launch_bounds__(256) void k_gemm1(const float* __restrict__ A,
                                               const float* __restrict__ B) {
    __shared__ float As[BK][BM + 1];
    __shared__ float Bs[BK][BN];
    int tx = threadIdx.x % 16;        // col group
    int ty = threadIdx.x / 16;        // row group
    int rowBase = blockIdx.x * BM;
    int colBase = blockIdx.y * BN;
    float acc[4][4] = {};
    for (int k0 = 0; k0 < F1; k0 += BK) {
        #pragma unroll
        for (int i = threadIdx.x; i < BM * BK; i += 256) {
            int m = i / BK, kk = i % BK;
            int gr = rowBase + m;
            As[kk][m] = (gr < NN) ? A[gr * F1 + k0 + kk] : 0.f;
        }
        #pragma unroll
        for (int i = threadIdx.x; i < BK * BN; i += 256) {
            int kk = i / BN, c = i % BN;
            Bs[kk][c] = B[(k0 + kk) * F2 + colBase + c];
        }
        __syncthreads();
        #pragma unroll
        for (int kk = 0; kk < BK; kk++) {
            float a[4], b[4];
            #pragma unroll
            for (int i = 0; i < 4; i++) a[i] = As[kk][ty * 4 + i];
            #pragma unroll
            for (int j = 0; j < 4; j++) b[j] = Bs[kk][tx * 4 + j];
            #pragma unroll
            for (int i = 0; i < 4; i++)
                #pragma unroll
                for (int j = 0; j < 4; j++)
                    acc[i][j] += a[i] * b[j];
        }
        __syncthreads();
    }
    #pragma unroll
    for (int i = 0; i < 4; i++) {
        int gr = rowBase + ty * 4 + i;
        if (gr < NN) {
            #pragma unroll
            for (int j = 0; j < 4; j++)
                g_h1[(size_t)gr * F2 + colBase + tx * 4 + j] = acc[i][j];
        }
    }
}

// ---------------- alpha_src / alpha_dst for layer 1 (warp per node) --------
__global__ __launch_bounds__(256) void k_alpha1(const float* __restrict__ avS,
                                                const float* __restrict__ avD) {
    int n = (blockIdx.x * blockDim.x + threadIdx.x) >> 5;
    int lane = threadIdx.x & 31;
    if (n >= NN) return;
    float aS[4] = {0, 0, 0, 0}, aD[4] = {0, 0, 0, 0};
    #pragma unroll
    for (int k = 0; k < 8; k++) {
        int f = lane + 32 * k;            // head = k>>1
        float v = g_h1[(size_t)n * F2 + f];
        aS[k >> 1] += v * avS[f];
        aD[k >> 1] += v * avD[f];
    }
    #pragma unroll
    for (int h = 0; h < 4; h++) {
        #pragma unroll
        for (int o = 16; o; o >>= 1) {
            aS[h] += __shfl_xor_sync(0xffffffffu, aS[h], o);
            aD[h] += __shfl_xor_sync(0xffffffffu, aD[h], o);
        }
    }
    if (lane == 0) {
        *(float4*)(g_as1 + 4 * n) = make_float4(aS[0], aS[1], aS[2], aS[3]);
        *(float4*)(g_ad1 + 4 * n) = make_float4(aD[0], aD[1], aD[2], aD[3]);
    }
}

// ---------------- layer-1 softmax + aggregation (warp per dst node) --------
__global__ __launch_bounds__(256) void k_agg1(const float* __restrict__ b1) {
    int n = (blockIdx.x * blockDim.x + threadIdx.x) >> 5;
    int lane = threadIdx.x & 31;
    if (n >= NN) return;
    int beg = g_rowptr[n], end = g_rowptr[n + 1];
    float4 ad = *(const float4*)(g_ad1 + 4 * n);

    // pass 1: per-head max over incoming edges (lanes parallel over edges)
    float m0 = -1e30f, m1 = -1e30f, m2 = -1e30f, m3 = -1e30f;
    for (int e = beg + lane; e < end; e += 32) {
        int s = g_csr[e];
        float4 as = *(const float4*)(g_as1 + 4 * s);
        m0 = fmaxf(m0, lrelu(as.x + ad.x));
        m1 = fmaxf(m1, lrelu(as.y + ad.y));
        m2 = fmaxf(m2, lrelu(as.z + ad.z));
        m3 = fmaxf(m3, lrelu(as.w + ad.w));
    }
    #pragma unroll
    for (int o = 16; o; o >>= 1) {
        m0 = fmaxf(m0, __shfl_xor_sync(0xffffffffu, m0, o));
        m1 = fmaxf(m1, __shfl_xor_sync(0xffffffffu, m1, o));
        m2 = fmaxf(m2, __shfl_xor_sync(0xffffffffu, m2, o));
        m3 = fmaxf(m3, __shfl_xor_sync(0xffffffffu, m3, o));
    }

    // pass 2: per-head sum of exp(e - m)
    float s0 = 0, s1 = 0, s2 = 0, s3 = 0;
    for (int e = beg + lane; e < end; e += 32) {
        int s = g_csr[e];
        float4 as = *(const float4*)(g_as1 + 4 * s);
        s0 += expf(lrelu(as.x + ad.x) - m0);
        s1 += expf(lrelu(as.y + ad.y) - m1);
        s2 += expf(lrelu(as.z + ad.z) - m2);
        s3 += expf(lrelu(as.w + ad.w) - m3);
    }
    #pragma unroll
    for (int o = 16; o; o >>= 1) {
        s0 += __shfl_xor_sync(0xffffffffu, s0, o);
        s1 += __shfl_xor_sync(0xffffffffu, s1, o);
        s2 += __shfl_xor_sync(0xffffffffu, s2, o);
        s3 += __shfl_xor_sync(0xffffffffu, s3, o);
    }
    float r0 = 1.f / s0, r1 = 1.f / s1, r2 = 1.f / s2, r3 = 1.f / s3;

    // pass 3: edges serial, lanes over 256 features (2 x float4 per lane).
    // lane's first float4 covers features [4*lane,4*lane+4) -> head lane/16 (0 or 1)
    // second float4 covers [128+4*lane, ...)                -> head 2 + lane/16
    bool lo = lane < 16;
    float mA = lo ? m0 : m1, mB = lo ? m2 : m3;
    float rA = lo ? r0 : r1, rB = lo ? r2 : r3;
    float adA = lo ? ad.x : ad.y, adB = lo ? ad.z : ad.w;

    float4 acc0 = {0, 0, 0, 0}, acc1 = {0, 0, 0, 0};
    const float4* h1v = (const float4*)g_h1;
    for (int e = beg; e < end; e++) {
        int s = g_csr[e];
        float4 as = *(const float4*)(g_as1 + 4 * s);
        float aA = expf(lrelu((lo ? as.x : as.y) + adA) - mA) * rA;
        float aB = expf(lrelu((lo ? as.z : as.w) + adB) - mB) * rB;
        float4 v0 = h1v[(size_t)s * 64 + lane];
        float4 v1 = h1v[(size_t)s * 64 + 32 + lane];
        acc0.x += v0.x * aA; acc0.y += v0.y * aA; acc0.z += v0.z * aA; acc0.w += v0.w * aA;
        acc1.x += v1.x * aB; acc1.y += v1.y * aB; acc1.z += v1.z * aB; acc1.w += v1.w * aB;
    }

    const float4* b1v = (const float4*)b1;
    float4 bb0 = b1v[lane], bb1 = b1v[32 + lane];
    float4 o0, o1;
    o0.x = elu1(acc0.x + bb0.x); o0.y = elu1(acc0.y + bb0.y);
    o0.z = elu1(acc0.z + bb0.z); o0.w = elu1(acc0.w + bb0.w);
    o1.x = elu1(acc1.x + bb1.x); o1.y = elu1(acc1.y + bb1.y);
    o1.z = elu1(acc1.z + bb1.z); o1.w = elu1(acc1.w + bb1.w);
    ((float4*)g_h2)[(size_t)n * 64 + lane]      = o0;
    ((float4*)g_h2)[(size_t)n * 64 + 32 + lane] = o1;
}

// ---------------- layer-2 linear (256 -> 2) + alphas (warp per node) --------
__global__ __launch_bounds__(256) void k_gemm2(const float* __restrict__ W2,
                                               const float* __restrict__ aS,
                                               const float* __restrict__ aD) {
    int n = (blockIdx.x * blockDim.x + threadIdx.x) >> 5;
    int lane = threadIdx.x & 31;
    if (n >= NN) return;
    float s0 = 0, s1 = 0;
    #pragma unroll
    for (int k = 0; k < 8; k++) {
        int f = lane + 32 * k;
        float v = g_h2[(size_t)n * F2 + f];
        float2 w = *(const float2*)(W2 + 2 * f);
        s0 += v * w.x;
        s1 += v * w.y;
    }
    #pragma unroll
    for (int o = 16; o; o >>= 1) {
        s0 += __shfl_xor_sync(0xffffffffu, s0, o);
        s1 += __shfl_xor_sync(0xffffffffu, s1, o);
    }
    if (lane == 0) {
        g_h3[2 * n] = s0;
        g_h3[2 * n + 1] = s1;
        g_as2[n] = s0 * aS[0] + s1 * aS[1];
        g_ad2[n] = s0 * aD[0] + s1 * aD[1];
    }
}

// ---------------- layer-2 softmax + aggregation (warp per dst node) --------
__global__ __launch_bounds__(256) void k_agg2(float* __restrict__ out,
                                              const float* __restrict__ b2) {
    int n = (blockIdx.x * blockDim.x + threadIdx.x) >> 5;
    int lane = threadIdx.x & 31;
    if (n >= NN) return;
    int beg = g_rowptr[n], end = g_rowptr[n + 1];
    float adv = g_ad2[n];

    float m = -1e30f;
    for (int e = beg + lane; e < end; e += 32)
        m = fmaxf(m, lrelu(g_as2[g_csr[e]] + adv));
    #pragma unroll
    for (int o = 16; o; o >>= 1)
        m = fmaxf(m, __shfl_xor_sync(0xffffffffu, m, o));

    float s = 0, p0 = 0, p1 = 0;
    for (int e = beg + lane; e < end; e += 32) {
        int sn = g_csr[e];
        float ex = expf(lrelu(g_as2[sn] + adv) - m);
        float2 h = *(const float2*)(g_h3 + 2 * sn);
        s += ex;
        p0 += ex * h.x;
        p1 += ex * h.y;
    }
    #pragma unroll
    for (int o = 16; o; o >>= 1) {
        s  += __shfl_xor_sync(0xffffffffu, s, o);
        p0 += __shfl_xor_sync(0xffffffffu, p0, o);
        p1 += __shfl_xor_sync(0xffffffffu, p1, o);
    }
    if (lane == 0) {
        float inv = 1.f / s;
        out[2 * n]     = p0 * inv + b2[0];
        out[2 * n + 1] = p1 * inv + b2[1];
    }
}

// ---------------- launch ----------------------------------------------------
extern "C" void kernel_launch(void* const* d_in, const int* in_sizes, int n_in,
                              void* d_out, int out_size) {
    const float* x   = (const float*)d_in[0];
    const int*   ei  = (const int*)  d_in[1];
    const float* W1  = (const float*)d_in[2];
    const float* aS1 = (const float*)d_in[3];
    const float* aD1 = (const float*)d_in[4];
    const float* b1  = (const float*)d_in[5];
    const float* W2  = (const float*)d_in[6];
    const float* aS2 = (const float*)d_in[7];
    const float* aD2 = (const float*)d_in[8];
    const float* b2  = (const float*)d_in[9];
    float* out = (float*)d_out;

    // CSR build (graph is identical across both layers)
    k_init_cnt<<<(NN + 255) / 256, 256>>>();
    k_degree<<<(EE + 255) / 256, 256>>>(ei);
    k_scan<<<1, 1024>>>();
    k_scatter<<<(ETOT + 255) / 256, 256>>>(ei);

    // layer 1
    k_gemm1<<<dim3((NN + BM - 1) / BM, F2 / BN), 256>>>(x, W1);
    int warpGrid = (NN * 32 + 255) / 256;
    k_alpha1<<<warpGrid, 256>>>(aS1, aD1);
    k_agg1<<<warpGrid, 256>>>(b1);

    // layer 2
    k_gemm2<<<warpGrid, 256>>>(W2, aS2, aD2);
    k_agg2<<<warpGrid, 256>>>(out, b2);
}

// round 5
// speedup vs baseline: 1.1118x; 1.1118x over previous
#include <cuda_runtime.h>
#include <math.h>
#include <stdint.h>

// Problem constants (fixed by the dataset)
#define NN   100000
#define EE   1600000
#define ETOT (EE + NN)          // edges + self loops
#define F1   128                // input features
#define F2   256                // HEADS*HID
#define NEG_SLOPE 0.2f

// ---------------- scratch (device globals; no allocations allowed) ----------
__device__ float g_h1[(size_t)NN * F2];   // layer1 linear output  [N,256]
__device__ float g_h2[(size_t)NN * F2];   // elu(agg1 + b1)        [N,256]
__device__ float g_as1[NN * 4];
__device__ float g_ad1[NN * 4];
__device__ float g_h3[NN * 2];
__device__ float g_as2[NN];
__device__ float g_ad2[NN];
__device__ int   g_cnt[NN];
__device__ int   g_rowptr[NN + 1];
__device__ int   g_cursor[NN];
__device__ int   g_csr[ETOT];             // src node id per incoming edge, grouped by dst

__device__ __forceinline__ float lrelu(float x) { return x > 0.f ? x : NEG_SLOPE * x; }
__device__ __forceinline__ float elu1(float x)  { return x > 0.f ? x : expm1f(x); }

// ---------------- CSR construction ------------------------------------------
__global__ void k_init_cnt() {
    int i = blockIdx.x * blockDim.x + threadIdx.x;
    if (i < NN) g_cnt[i] = 1;   // self loop
}

__global__ void k_degree(const int* __restrict__ ei) {
    int i = blockIdx.x * blockDim.x + threadIdx.x;
    if (i < EE) atomicAdd(&g_cnt[ei[EE + i]], 1);
}

// single-block exclusive scan over g_cnt -> g_rowptr / g_cursor
__global__ void k_scan() {
    __shared__ int part[1024];
    int tid = threadIdx.x;
    const int chunk = (NN + 1023) / 1024;
    int start = tid * chunk;
    int end   = min(start + chunk, NN);
    int sum = 0;
    for (int i = start; i < end; i++) sum += g_cnt[i];
    part[tid] = sum;
    __syncthreads();
    for (int off = 1; off < 1024; off <<= 1) {
        int v = 0;
        if (tid >= off) v = part[tid - off];
        __syncthreads();
        if (tid >= off) part[tid] += v;
        __syncthreads();
    }
    int run = (tid == 0) ? 0 : part[tid - 1];
    for (int i = start; i < end; i++) {
        g_rowptr[i] = run;
        g_cursor[i] = run;
        run += g_cnt[i];
    }
    if (tid == 1023) g_rowptr[NN] = part[1023];
}

__global__ void k_scatter(const int* __restrict__ ei) {
    int i = blockIdx.x * blockDim.x + threadIdx.x;
    if (i < EE) {
        int s = ei[i];
        int d = ei[EE + i];
        int p = atomicAdd(&g_cursor[d], 1);
        g_csr[p] = s;
    } else if (i < ETOT) {
        int n = i - EE;
        int p = atomicAdd(&g_cursor[n], 1);
        g_csr[p] = n;   // self loop
    }
}

// ---------------- GEMM1 (tensor cores, tf32x3): h1 = x @ W1 -----------------
// 100000x128 @ 128x256, fp32 accuracy via hi/lo tf32 split (3 MMAs).
// Block tile 128x64x32, 8 warps of 64x16 each (4 m-tiles x 2 n-tiles of m16n8k8).
#define GBM 128
#define GBN 64
#define GBK 32
#define ASTRIDE 36   // floats; (4m+k)%32 distinct for 8 rows x 4 cols -> no conflicts
#define BSTRIDE 72   // floats; (8k+n)%32 distinct for 4 rows x 8 cols -> no conflicts

__device__ __forceinline__ uint32_t f2tf32(float f) {
    uint32_t r;
    asm("cvt.rna.tf32.f32 %0, %1;" : "=r"(r) : "f"(f));
    return r;
}
__device__ __forceinline__ void split_tf32(float f, uint32_t& hi, uint32_t& lo) {
    hi = f2tf32(f);
    lo = f2tf32(f - __uint_as_float(hi));
}
__device__ __forceinline__ void mma_tf32(float* c, uint32_t a0, uint32_t a1,
                                         uint32_t a2, uint32_t a3,
                                         uint32_t b0, uint32_t b1) {
    asm volatile(
        "mma.sync.aligned.m16n8k8.row.col.f32.tf32.tf32.f32 "
        "{%0,%1,%2,%3}, {%4,%5,%6,%7}, {%8,%9}, {%0,%1,%2,%3};"
        : "+f"(c[0]), "+f"(c[1]), "+f"(c[2]), "+f"(c[3])
        : "r"(a0), "r"(a1), "r"(a2), "r"(a3), "r"(b0), "r"(b1));
}

__global__ __launch_bounds__(256) void k_gemm1_tc(const float* __restrict__ A,
                                                  const float* __restrict__ B) {
    __shared__ float As[GBM * ASTRIDE];
    __shared__ float Bs[GBK * BSTRIDE];
    const int tid  = threadIdx.x;
    const int wid  = tid >> 5;
    const int lane = tid & 31;
    const int grp  = lane >> 2;
    const int tig  = lane & 3;
    const int wm   = wid & 1;        // 0..1 -> row offset 64*wm
    const int wn   = wid >> 1;       // 0..3 -> col offset 16*wn
    const int m0   = blockIdx.x * GBM;
    const int n0   = blockIdx.y * GBN;

    float acc[4][2][4];
    #pragma unroll
    for (int i = 0; i < 4; i++)
        #pragma unroll
        for (int j = 0; j < 2; j++)
            #pragma unroll
            for (int k = 0; k < 4; k++) acc[i][j][k] = 0.f;

    // per-thread global-load coords
    // A: 4 float4: f = tid + i*256; arow = f>>3 (0..127), ac4 = f&7 (k chunk)
    // B: 2 float4: f = tid + i*256; brow = f>>4 (0..31),  bc4 = f&15 (n chunk)
    float4 pa[4], pb[2];

    auto loadA = [&](int k0, float4* r) {
        #pragma unroll
        for (int i = 0; i < 4; i++) {
            int f = tid + i * 256;
            int row = f >> 3, c4 = f & 7;
            int gr = m0 + row;
            r[i] = (gr < NN) ? *(const float4*)(A + (size_t)gr * F1 + k0 + 4 * c4)
                             : make_float4(0.f, 0.f, 0.f, 0.f);
        }
    };
    auto loadB = [&](int k0, float4* r) {
        #pragma unroll
        for (int i = 0; i < 2; i++) {
            int f = tid + i * 256;
            int row = f >> 4, c4 = f & 15;
            r[i] = *(const float4*)(B + (size_t)(k0 + row) * F2 + n0 + 4 * c4);
        }
    };

    loadA(0, pa);
    loadB(0, pb);

    for (int k0 = 0; k0 < F1; k0 += GBK) {
        // stage prefetched tile into smem
        #pragma unroll
        for (int i = 0; i < 4; i++) {
            int f = tid + i * 256;
            int row = f >> 3, c4 = f & 7;
            *(float4*)(As + row * ASTRIDE + 4 * c4) = pa[i];
        }
        #pragma unroll
        for (int i = 0; i < 2; i++) {
            int f = tid + i * 256;
            int row = f >> 4, c4 = f & 15;
            *(float4*)(Bs + row * BSTRIDE + 4 * c4) = pb[i];
        }
        __syncthreads();

        if (k0 + GBK < F1) {
            loadA(k0 + GBK, pa);
            loadB(k0 + GBK, pb);
        }

        #pragma unroll
        for (int ks = 0; ks < GBK / 8; ks++) {
            const int kb = ks * 8;
            uint32_t ahi[4][4], alo[4][4];
            #pragma unroll
            for (int mt = 0; mt < 4; mt++) {
                int r = wm * 64 + mt * 16 + grp;
                float a0 = As[r * ASTRIDE + kb + tig];
                float a1 = As[(r + 8) * ASTRIDE + kb + tig];
                float a2 = As[r * ASTRIDE + kb + tig + 4];
                float a3 = As[(r + 8) * ASTRIDE + kb + tig + 4];
                split_tf32(a0, ahi[mt][0], alo[mt][0]);
                split_tf32(a1, ahi[mt][1], alo[mt][1]);
                split_tf32(a2, ahi[mt][2], alo[mt][2]);
                split_tf32(a3, ahi[mt][3], alo[mt][3]);
            }
            uint32_t bhi[2][2], blo[2][2];
            #pragma unroll
            for (int nt = 0; nt < 2; nt++) {
                int c = wn * 16 + nt * 8 + grp;
                float b0 = Bs[(kb + tig) * BSTRIDE + c];
                float b1 = Bs[(kb + tig + 4) * BSTRIDE + c];
                split_tf32(b0, bhi[nt][0], blo[nt][0]);
                split_tf32(b1, bhi[nt][1], blo[nt][1]);
            }
            #pragma unroll
            for (int mt = 0; mt < 4; mt++) {
                #pragma unroll
                for (int nt = 0; nt < 2; nt++) {
                    float* c = acc[mt][nt];
                    mma_tf32(c, ahi[mt][0], ahi[mt][1], ahi[mt][2], ahi[mt][3],
                             bhi[nt][0], bhi[nt][1]);
                    mma_tf32(c, ahi[mt][0], ahi[mt][1], ahi[mt][2], ahi[mt][3],
                             blo[nt][0], blo[nt][1]);
                    mma_tf32(c, alo[mt][0], alo[mt][1], alo[mt][2], alo[mt][3],
                             bhi[nt][0], bhi[nt][1]);
                }
            }
        }
        __syncthreads();
    }

    // epilogue: c0,c1 -> (row, 2tig), (row, 2tig+1); c2,c3 -> row+8
    #pragma unroll
    for (int mt = 0; mt < 4; mt++) {
        int r = m0 + wm * 64 + mt * 16 + grp;
        #pragma unroll
        for (int nt = 0; nt < 2; nt++) {
            int c = n0 + wn * 16 + nt * 8 + 2 * tig;
            if (r < NN)
                *(float2*)(g_h1 + (size_t)r * F2 + c) =
                    make_float2(acc[mt][nt][0], acc[mt][nt][1]);
            if (r + 8 < NN)
                *(float2*)(g_h1 + (size_t)(r + 8) * F2 + c) =
                    make_float2(acc[mt][nt][2], acc[mt][nt][3]);
        }
    }
}

// ---------------- alpha_src / alpha_dst for layer 1 (warp per node) --------
__global__ __launch_bounds__(256) void k_alpha1(const float* __restrict__ avS,
                                                const float* __restrict__ avD) {
    int n = (blockIdx.x * blockDim.x + threadIdx.x) >> 5;
    int lane = threadIdx.x & 31;
    if (n >= NN) return;
    float aS[4] = {0, 0, 0, 0}, aD[4] = {0, 0, 0, 0};
    #pragma unroll
    for (int k = 0; k < 8; k++) {
        int f = lane + 32 * k;            // head = k>>1
        float v = g_h1[(size_t)n * F2 + f];
        aS[k >> 1] += v * avS[f];
        aD[k >> 1] += v * avD[f];
    }
    #pragma unroll
    for (int h = 0; h < 4; h++) {
        #pragma unroll
        for (int o = 16; o; o >>= 1) {
            aS[h] += __shfl_xor_sync(0xffffffffu, aS[h], o);
            aD[h] += __shfl_xor_sync(0xffffffffu, aD[h], o);
        }
    }
    if (lane == 0) {
        *(float4*)(g_as1 + 4 * n) = make_float4(aS[0], aS[1], aS[2], aS[3]);
        *(float4*)(g_ad1 + 4 * n) = make_float4(aD[0], aD[1], aD[2], aD[3]);
    }
}

// ---------------- layer-1 softmax + aggregation (warp per dst node) --------
__global__ __launch_bounds__(256) void k_agg1(const float* __restrict__ b1) {
    int n = (blockIdx.x * blockDim.x + threadIdx.x) >> 5;
    int lane = threadIdx.x & 31;
    if (n >= NN) return;
    int beg = g_rowptr[n], end = g_rowptr[n + 1];
    float4 ad = *(const float4*)(g_ad1 + 4 * n);

    // pass 1: per-head max over incoming edges (lanes parallel over edges)
    float m0 = -1e30f, m1 = -1e30f, m2 = -1e30f, m3 = -1e30f;
    for (int e = beg + lane; e < end; e += 32) {
        int s = g_csr[e];
        float4 as = *(const float4*)(g_as1 + 4 * s);
        m0 = fmaxf(m0, lrelu(as.x + ad.x));
        m1 = fmaxf(m1, lrelu(as.y + ad.y));
        m2 = fmaxf(m2, lrelu(as.z + ad.z));
        m3 = fmaxf(m3, lrelu(as.w + ad.w));
    }
    #pragma unroll
    for (int o = 16; o; o >>= 1) {
        m0 = fmaxf(m0, __shfl_xor_sync(0xffffffffu, m0, o));
        m1 = fmaxf(m1, __shfl_xor_sync(0xffffffffu, m1, o));
        m2 = fmaxf(m2, __shfl_xor_sync(0xffffffffu, m2, o));
        m3 = fmaxf(m3, __shfl_xor_sync(0xffffffffu, m3, o));
    }

    // pass 2: per-head sum of exp(e - m)
    float s0 = 0, s1 = 0, s2 = 0, s3 = 0;
    for (int e = beg + lane; e < end; e += 32) {
        int s = g_csr[e];
        float4 as = *(const float4*)(g_as1 + 4 * s);
        s0 += expf(lrelu(as.x + ad.x) - m0);
        s1 += expf(lrelu(as.y + ad.y) - m1);
        s2 += expf(lrelu(as.z + ad.z) - m2);
        s3 += expf(lrelu(as.w + ad.w) - m3);
    }
    #pragma unroll
    for (int o = 16; o; o >>= 1) {
        s0 += __shfl_xor_sync(0xffffffffu, s0, o);
        s1 += __shfl_xor_sync(0xffffffffu, s1, o);
        s2 += __shfl_xor_sync(0xffffffffu, s2, o);
        s3 += __shfl_xor_sync(0xffffffffu, s3, o);
    }
    float r0 = 1.f / s0, r1 = 1.f / s1, r2 = 1.f / s2, r3 = 1.f / s3;

    // pass 3: edges serial, lanes over 256 features (2 x float4 per lane).
    bool lo = lane < 16;
    float mA = lo ? m0 : m1, mB = lo ? m2 : m3;
    float rA = lo ? r0 : r1, rB = lo ? r2 : r3;
    float adA = lo ? ad.x : ad.y, adB = lo ? ad.z : ad.w;

    float4 acc0 = {0, 0, 0, 0}, acc1 = {0, 0, 0, 0};
    const float4* h1v = (const float4*)g_h1;
    #pragma unroll 2
    for (int e = beg; e < end; e++) {
        int s = g_csr[e];
        float4 as = *(const float4*)(g_as1 + 4 * s);
        float aA = expf(lrelu((lo ? as.x : as.y) + adA) - mA) * rA;
        float aB = expf(lrelu((lo ? as.z : as.w) + adB) - mB) * rB;
        float4 v0 = h1v[(size_t)s * 64 + lane];
        float4 v1 = h1v[(size_t)s * 64 + 32 + lane];
        acc0.x += v0.x * aA; acc0.y += v0.y * aA; acc0.z += v0.z * aA; acc0.w += v0.w * aA;
        acc1.x += v1.x * aB; acc1.y += v1.y * aB; acc1.z += v1.z * aB; acc1.w += v1.w * aB;
    }

    const float4* b1v = (const float4*)b1;
    float4 bb0 = b1v[lane], bb1 = b1v[32 + lane];
    float4 o0, o1;
    o0.x = elu1(acc0.x + bb0.x); o0.y = elu1(acc0.y + bb0.y);
    o0.z = elu1(acc0.z + bb0.z); o0.w = elu1(acc0.w + bb0.w);
    o1.x = elu1(acc1.x + bb1.x); o1.y = elu1(acc1.y + bb1.y);
    o1.z = elu1(acc1.z + bb1.z); o1.w = elu1(acc1.w + bb1.w);
    ((float4*)g_h2)[(size_t)n * 64 + lane]      = o0;
    ((float4*)g_h2)[(size_t)n * 64 + 32 + lane] = o1;
}

// ---------------- layer-2 linear (256 -> 2) + alphas (warp per node) --------
__global__ __launch_bounds__(256) void k_gemm2(const float* __restrict__ W2,
                                               const float* __restrict__ aS,
                                               const float* __restrict__ aD) {
    int n = (blockIdx.x * blockDim.x + threadIdx.x) >> 5;
    int lane = threadIdx.x & 31;
    if (n >= NN) return;
    float s0 = 0, s1 = 0;
    #pragma unroll
    for (int k = 0; k < 8; k++) {
        int f = lane + 32 * k;
        float v = g_h2[(size_t)n * F2 + f];
        float2 w = *(const float2*)(W2 + 2 * f);
        s0 += v * w.x;
        s1 += v * w.y;
    }
    #pragma unroll
    for (int o = 16; o; o >>= 1) {
        s0 += __shfl_xor_sync(0xffffffffu, s0, o);
        s1 += __shfl_xor_sync(0xffffffffu, s1, o);
    }
    if (lane == 0) {
        g_h3[2 * n] = s0;
        g_h3[2 * n + 1] = s1;
        g_as2[n] = s0 * aS[0] + s1 * aS[1];
        g_ad2[n] = s0 * aD[0] + s1 * aD[1];
    }
}

// ---------------- layer-2 softmax + aggregation (warp per dst node) --------
__global__ __launch_bounds__(256) void k_agg2(float* __restrict__ out,
                                              const float* __restrict__ b2) {
    int n = (blockIdx.x * blockDim.x + threadIdx.x) >> 5;
    int lane = threadIdx.x & 31;
    if (n >= NN) return;
    int beg = g_rowptr[n], end = g_rowptr[n + 1];
    float adv = g_ad2[n];

    float m = -1e30f;
    for (int e = beg + lane; e < end; e += 32)
        m = fmaxf(m, lrelu(g_as2[g_csr[e]] + adv));
    #pragma unroll
    for (int o = 16; o; o >>= 1)
        m = fmaxf(m, __shfl_xor_sync(0xffffffffu, m, o));

    float s = 0, p0 = 0, p1 = 0;
    for (int e = beg + lane; e < end; e += 32) {
        int sn = g_csr[e];
        float ex = expf(lrelu(g_as2[sn] + adv) - m);
        float2 h = *(const float2*)(g_h3 + 2 * sn);
        s += ex;
        p0 += ex * h.x;
        p1 += ex * h.y;
    }
    #pragma unroll
    for (int o = 16; o; o >>= 1) {
        s  += __shfl_xor_sync(0xffffffffu, s, o);
        p0 += __shfl_xor_sync(0xffffffffu, p0, o);
        p1 += __shfl_xor_sync(0xffffffffu, p1, o);
    }
    if (lane == 0) {
        float inv = 1.f / s;
        out[2 * n]     = p0 * inv + b2[0];
        out[2 * n + 1] = p1 * inv + b2[1];
    }
}

// ---------------- launch ----------------------------------------------------
extern "C" void kernel_launch(void* const* d_in, const int* in_sizes, int n_in,
                              void* d_out, int out_size) {
    const float* x   = (const float*)d_in[0];
    const int*   ei  = (const int*)  d_in[1];
    const float* W1  = (const float*)d_in[2];
    const float* aS1 = (const float*)d_in[3];
    const float* aD1 = (const float*)d_in[4];
    const float* b1  = (const float*)d_in[5];
    const float* W2  = (const float*)d_in[6];
    const float* aS2 = (const float*)d_in[7];
    const float* aD2 = (const float*)d_in[8];
    const float* b2  = (const float*)d_in[9];
    float* out = (float*)d_out;

    // CSR build (graph is identical across both layers)
    k_init_cnt<<<(NN + 255) / 256, 256>>>();
    k_degree<<<(EE + 255) / 256, 256>>>(ei);
    k_scan<<<1, 1024>>>();
    k_scatter<<<(ETOT + 255) / 256, 256>>>(ei);

    // layer 1
    k_gemm1_tc<<<dim3((NN + GBM - 1) / GBM, F2 / GBN), 256>>>(x, W1);
    int warpGrid = (NN * 32 + 255) / 256;
    k_alpha1<<<warpGrid, 256>>>(aS1, aD1);
    k_agg1<<<warpGrid, 256>>>(b1);

    // layer 2
    k_gemm2<<<warpGrid, 256>>>(W2, aS2, aD2);
    k_agg2<<<warpGrid, 256>>>(out, b2);
}